// round 3
// baseline (speedup 1.0000x reference)
#include <cuda_runtime.h>
#include <cuda_bf16.h>

// GaussianKernelLoss: B=32, N=16, H=W=256, SIGMA=0.1, RADIUS=0.2
// Inputs (metadata order):
//   d_in[0] = pred_landmarks   [32,16,2] float32
//   d_in[1] = target_landmarks [32,16,2] float32
//   d_in[2] = visibility       [32,16]   float32
//   d_in[3] = coord_grid       [2,256,256] float32  (== linspace: i/255)
// Output: scalar float32.

#define BN     512
#define RADIUS 0.2f
#define R2     (0.2f * 0.2f)
#define COEF   (-50.0f)        // -1/(2*sigma^2)
#define INV255 (1.0f / 255.0f)
#define NROW   7               // 7*16 = 112 >= max bbox height (106)
#define NCOL   4               // 4*32 = 128 >= max bbox width  (106)

__device__ float g_partial[BN];
__device__ int   g_count;      // zero-init; last block resets each launch

__global__ __launch_bounds__(512, 3)
void gkl_fused_kernel(const float* __restrict__ pred,
                      const float* __restrict__ tgt,
                      const float* __restrict__ vis,
                      const float* __restrict__ grid,
                      float* __restrict__ out)
{
    const int lm  = blockIdx.x;
    const int tid = threadIdx.x;
    const int cx  = tid & 31;   // lane -> column subset
    const int cy  = tid >> 5;   // warp -> row subset

    __shared__ float redN[16], redD[16];
    __shared__ int   sIsLast;

    float num = 0.0f, den = 0.0f;
    const float v = vis[lm];

    if (v >= 0.5f) {
        const float2 t2v = ((const float2*)tgt)[lm];
        const float2 p2v = ((const float2*)pred)[lm];
        const float tx = t2v.x, ty = t2v.y;
        const float px = p2v.x, py = p2v.y;

        // Bounding box of the radius disk (exact d<=R mask applied per-pixel).
        const int x0 = max(0,   (int)floorf((tx - RADIUS) * 255.0f) - 1);
        const int y0 = max(0,   (int)floorf((ty - RADIUS) * 255.0f) - 1);
        const int x1 = min(255, (int)ceilf ((tx + RADIUS) * 255.0f) + 1);
        const int y1 = min(255, (int)ceilf ((ty + RADIUS) * 255.0f) + 1);
        const int bw = x1 - x0 + 1;
        const int bh = y1 - y0 + 1;

        // Column tables in registers: lane cx owns columns cx + 32k.
        // Out-of-range columns poisoned (Ex=0, T2=huge) -> contribute 0.
        float cT2[NCOL], cP2[NCOL], cEx[NCOL];
        #pragma unroll
        for (int k = 0; k < NCOL; k++) {
            const int j   = cx + 32 * k;
            const bool ok = (j < bw);
            const float xv = (float)(x0 + j) * INV255;   // coord_grid == linspace
            const float dt = xv - tx;
            const float dp = xv - px;
            cT2[k] = ok ? dt * dt : 1e9f;
            cP2[k] = dp * dp;
            cEx[k] = ok ? __expf(COEF * dt * dt) : 0.0f;
        }

        // Pixel loop: fully unrolled 7 rows x 4 cols, no shared, no barriers.
        #pragma unroll
        for (int r = 0; r < NROW; r++) {
            const int i   = cy + 16 * r;
            const bool rk = (i < bh);
            const float yv  = (float)(y0 + i) * INV255;
            const float dty = yv - ty;
            const float dpy = yv - py;
            const float t2y = rk ? dty * dty : 1e9f;
            const float p2y = dpy * dpy;
            const float ey  = rk ? __expf(COEF * dty * dty) : 0.0f;
            #pragma unroll
            for (int k = 0; k < NCOL; k++) {
                const float d2t = cT2[k] + t2y;
                const float w   = cEx[k] * ey;
                const float d2p = cP2[k] + p2y;
                float d;
                asm("sqrt.approx.f32 %0, %1;" : "=f"(d) : "f"(d2p));
                const bool in = (d2t <= R2);
                num += in ? w * d : 0.0f;
                den += in ? w     : 0.0f;
            }
        }
    }

    // Block reduction of (num, den) — uniform path for all blocks.
    #pragma unroll
    for (int o = 16; o; o >>= 1) {
        num += __shfl_xor_sync(0xffffffffu, num, o);
        den += __shfl_xor_sync(0xffffffffu, den, o);
    }
    if (cx == 0) { redN[cy] = num; redD[cy] = den; }
    __syncthreads();

    if (tid == 0) {
        float n = 0.0f, d = 0.0f;
        #pragma unroll
        for (int k = 0; k < 16; k++) { n += redN[k]; d += redD[k]; }
        g_partial[lm] = n / (d + 1e-8f);   // invisible: 0/1e-8 = 0
        __threadfence();
        const int c = atomicAdd(&g_count, 1);
        sIsLast = (c == BN - 1);
    }
    __syncthreads();

    // Last block folds all 512 partials into the scalar output.
    if (sIsLast) {
        float s = __ldcg(&g_partial[tid]);
        #pragma unroll
        for (int o = 16; o; o >>= 1) s += __shfl_xor_sync(0xffffffffu, s, o);
        if (cx == 0) redN[cy] = s;
        __syncthreads();
        if (tid < 16) {
            s = redN[tid];
            #pragma unroll
            for (int o = 8; o; o >>= 1) s += __shfl_xor_sync(0xffffu, s, o);
            if (tid == 0) {
                *out = s / (512.0f + 1e-8f);
                g_count = 0;               // reset for next graph replay
            }
        }
    }
}

extern "C" void kernel_launch(void* const* d_in, const int* in_sizes, int n_in,
                              void* d_out, int out_size)
{
    const float* pred = (const float*)d_in[0];
    const float* tgt  = (const float*)d_in[1];
    const float* vis  = (const float*)d_in[2];
    const float* grid = (const float*)d_in[3];
    gkl_fused_kernel<<<BN, 512>>>(pred, tgt, vis, grid, (float*)d_out);
}

// round 4
// speedup vs baseline: 1.0026x; 1.0026x over previous
#include <cuda_runtime.h>
#include <cuda_bf16.h>

// GaussianKernelLoss: B=32, N=16, H=W=256, SIGMA=0.1, RADIUS=0.2
// d_in[0]=pred [32,16,2] f32, d_in[1]=target [32,16,2] f32,
// d_in[2]=visibility [32,16] f32, d_in[3]=coord_grid [2,256,256] f32 (linspace i/255)
// Output: scalar f32.

#define BN     512
#define RADIUS 0.2f
#define R2     (0.2f * 0.2f)
#define COEF   (-50.0f)        // -1/(2*sigma^2)
#define INV255 (1.0f / 255.0f)
#define NCOL   4               // 4*32 = 128 >= max bbox width (~106)
#define NTHR   128             // 4 warps per block, 1 landmark per block

__device__ float g_partial[BN];
__device__ int   g_count;      // zero-init; last block resets each launch

__global__ __launch_bounds__(NTHR)
void gkl_fused_kernel(const float* __restrict__ pred,
                      const float* __restrict__ tgt,
                      const float* __restrict__ vis,
                      const float* __restrict__ grid,
                      float* __restrict__ out)
{
    const int lm  = blockIdx.x;
    const int tid = threadIdx.x;
    const int cx  = tid & 31;   // lane -> column subset
    const int cy  = tid >> 5;   // warp (0..3) -> row subset

    __shared__ float redN[4], redD[4];
    __shared__ int   sIsLast;

    float num = 0.0f, den = 0.0f;
    const float v = vis[lm];

    if (v >= 0.5f) {
        const float2 t2v = ((const float2*)tgt)[lm];
        const float2 p2v = ((const float2*)pred)[lm];
        const float tx = t2v.x, ty = t2v.y;
        const float px = p2v.x, py = p2v.y;

        // Bounding box of the radius disk (exact d<=R mask applied per-pixel).
        const int x0 = max(0,   (int)floorf((tx - RADIUS) * 255.0f) - 1);
        const int y0 = max(0,   (int)floorf((ty - RADIUS) * 255.0f) - 1);
        const int x1 = min(255, (int)ceilf ((tx + RADIUS) * 255.0f) + 1);
        const int y1 = min(255, (int)ceilf ((ty + RADIUS) * 255.0f) + 1);
        const int bw = x1 - x0 + 1;
        const int bh = y1 - y0 + 1;

        // Column tables in registers: lane cx owns columns cx + 32k.
        // Out-of-range columns poisoned (Ex=0, T2=huge) -> contribute 0.
        float cT2[NCOL], cP2[NCOL], cEx[NCOL];
        #pragma unroll
        for (int k = 0; k < NCOL; k++) {
            const int j   = cx + 32 * k;
            const bool ok = (j < bw);
            const float xv = (float)(x0 + j) * INV255;   // coord_grid == linspace
            const float dt = xv - tx;
            const float dp = xv - px;
            cT2[k] = ok ? dt * dt : 1e9f;
            cP2[k] = dp * dp;
            cEx[k] = ok ? __expf(COEF * dt * dt) : 0.0f;
        }

        // Row loop: warp cy owns rows cy + 4r, only real rows executed.
        for (int i = cy; i < bh; i += 4) {
            const float yv   = (float)(y0 + i) * INV255;
            const float dty  = yv - ty;
            const float dpy  = yv - py;
            const float t2y  = dty * dty;
            const float p2y  = dpy * dpy;
            const float ey   = __expf(COEF * t2y);
            const float limr = R2 - t2y;   // in-disk <=> cT2[k] <= limr
            #pragma unroll
            for (int k = 0; k < NCOL; k++) {
                const float d2p = cP2[k] + p2y;
                const float w   = cEx[k] * ey;
                float d;
                asm("sqrt.approx.f32 %0, %1;" : "=f"(d) : "f"(d2p));
                const bool in = (cT2[k] <= limr);
                num += in ? w * d : 0.0f;
                den += in ? w     : 0.0f;
            }
        }
    }

    // Block reduction (4 warps) — uniform path for all blocks.
    #pragma unroll
    for (int o = 16; o; o >>= 1) {
        num += __shfl_xor_sync(0xffffffffu, num, o);
        den += __shfl_xor_sync(0xffffffffu, den, o);
    }
    if (cx == 0) { redN[cy] = num; redD[cy] = den; }
    __syncthreads();

    if (tid == 0) {
        const float n = redN[0] + redN[1] + redN[2] + redN[3];
        const float d = redD[0] + redD[1] + redD[2] + redD[3];
        g_partial[lm] = n / (d + 1e-8f);   // invisible: 0/1e-8 = 0
        __threadfence();
        const int c = atomicAdd(&g_count, 1);
        sIsLast = (c == BN - 1);
    }
    __syncthreads();

    // Last block folds all 512 partials into the scalar output.
    if (sIsLast) {
        float s = __ldcg(&g_partial[tid])
                + __ldcg(&g_partial[tid + 128])
                + __ldcg(&g_partial[tid + 256])
                + __ldcg(&g_partial[tid + 384]);
        #pragma unroll
        for (int o = 16; o; o >>= 1) s += __shfl_xor_sync(0xffffffffu, s, o);
        if (cx == 0) redN[cy] = s;
        __syncthreads();
        if (tid == 0) {
            const float t = redN[0] + redN[1] + redN[2] + redN[3];
            *out = t / (512.0f + 1e-8f);
            g_count = 0;                   // reset for next graph replay
        }
    }
}

extern "C" void kernel_launch(void* const* d_in, const int* in_sizes, int n_in,
                              void* d_out, int out_size)
{
    const float* pred = (const float*)d_in[0];
    const float* tgt  = (const float*)d_in[1];
    const float* vis  = (const float*)d_in[2];
    const float* grid = (const float*)d_in[3];
    gkl_fused_kernel<<<BN, NTHR>>>(pred, tgt, vis, grid, (float*)d_out);
}

// round 5
// speedup vs baseline: 1.0212x; 1.0186x over previous
#include <cuda_runtime.h>
#include <cuda_bf16.h>

// GaussianKernelLoss: B=32, N=16, H=W=256, SIGMA=0.1, RADIUS=0.2
// d_in[0]=pred [32,16,2] f32, d_in[1]=target [32,16,2] f32,
// d_in[2]=visibility [32,16] f32, d_in[3]=coord_grid [2,256,256] f32 (linspace i/255)
// Output: scalar f32.

#define BN     512
#define RADIUS 0.2f
#define R2     (0.2f * 0.2f)
#define COEF   (-50.0f)        // -1/(2*sigma^2)
#define INV255 (1.0f / 255.0f)
#define NCOL   4               // 4*32 = 128 >= max bbox width (~106)
#define NTHR   256             // 8 warps per block, 1 landmark per block

__device__ float g_partial[BN];
__device__ int   g_count;      // zero-init; last block resets each launch

__global__ __launch_bounds__(NTHR)
void gkl_fused_kernel(const float* __restrict__ pred,
                      const float* __restrict__ tgt,
                      const float* __restrict__ vis,
                      const float* __restrict__ grid,
                      float* __restrict__ out)
{
    const int lm  = blockIdx.x;
    const int tid = threadIdx.x;
    const int cx  = tid & 31;   // lane -> column subset
    const int cy  = tid >> 5;   // warp (0..7) -> row subset

    __shared__ float redN[8], redD[8];
    __shared__ int   sIsLast;

    float num0 = 0.0f, den0 = 0.0f;   // two independent accumulator chains
    float num1 = 0.0f, den1 = 0.0f;
    const float v = vis[lm];

    if (v >= 0.5f) {
        const float2 t2v = ((const float2*)tgt)[lm];
        const float2 p2v = ((const float2*)pred)[lm];
        const float tx = t2v.x, ty = t2v.y;
        const float px = p2v.x, py = p2v.y;

        // Bounding box of the radius disk (exact d<=R mask applied per-pixel).
        const int x0 = max(0,   (int)floorf((tx - RADIUS) * 255.0f) - 1);
        const int y0 = max(0,   (int)floorf((ty - RADIUS) * 255.0f) - 1);
        const int x1 = min(255, (int)ceilf ((tx + RADIUS) * 255.0f) + 1);
        const int y1 = min(255, (int)ceilf ((ty + RADIUS) * 255.0f) + 1);
        const int bw = x1 - x0 + 1;
        const int bh = y1 - y0 + 1;

        // Column tables in registers: lane cx owns columns cx + 32k.
        // Out-of-range columns poisoned (Ex=0, T2=huge) -> contribute 0.
        float cT2[NCOL], cP2[NCOL], cEx[NCOL];
        #pragma unroll
        for (int k = 0; k < NCOL; k++) {
            const int j   = cx + 32 * k;
            const bool ok = (j < bw);
            const float xv = (float)(x0 + j) * INV255;   // coord_grid == linspace
            const float dt = xv - tx;
            const float dp = xv - px;
            cT2[k] = ok ? dt * dt : 1e9f;
            cP2[k] = dp * dp;
            cEx[k] = ok ? __expf(COEF * dt * dt) : 0.0f;
        }

        // Row bases: dty = dty0 + i*INV255 (single FFMA per row).
        const float dty0 = (float)y0 * INV255 - ty;
        const float dpy0 = (float)y0 * INV255 - py;

        // Row loop: warp cy owns rows cy + 8r; unrolled x2 with independent
        // accumulators so two ~60-cycle latency chains overlap.
        int i = cy;
        for (; i + 8 < bh; i += 16) {
            {   // row i
                const float dty = fmaf((float)i, INV255, dty0);
                const float dpy = fmaf((float)i, INV255, dpy0);
                const float t2y = dty * dty;
                const float p2y = dpy * dpy;
                const float ey  = __expf(COEF * t2y);
                const float lim = R2 - t2y;
                #pragma unroll
                for (int k = 0; k < NCOL; k++) {
                    const float d2p = cP2[k] + p2y;
                    const float w   = cEx[k] * ey;
                    float d;
                    asm("sqrt.approx.f32 %0, %1;" : "=f"(d) : "f"(d2p));
                    const bool in = (cT2[k] <= lim);
                    num0 += in ? w * d : 0.0f;
                    den0 += in ? w     : 0.0f;
                }
            }
            {   // row i+8
                const int   i2  = i + 8;
                const float dty = fmaf((float)i2, INV255, dty0);
                const float dpy = fmaf((float)i2, INV255, dpy0);
                const float t2y = dty * dty;
                const float p2y = dpy * dpy;
                const float ey  = __expf(COEF * t2y);
                const float lim = R2 - t2y;
                #pragma unroll
                for (int k = 0; k < NCOL; k++) {
                    const float d2p = cP2[k] + p2y;
                    const float w   = cEx[k] * ey;
                    float d;
                    asm("sqrt.approx.f32 %0, %1;" : "=f"(d) : "f"(d2p));
                    const bool in = (cT2[k] <= lim);
                    num1 += in ? w * d : 0.0f;
                    den1 += in ? w     : 0.0f;
                }
            }
        }
        if (i < bh) {   // remainder row
            const float dty = fmaf((float)i, INV255, dty0);
            const float dpy = fmaf((float)i, INV255, dpy0);
            const float t2y = dty * dty;
            const float p2y = dpy * dpy;
            const float ey  = __expf(COEF * t2y);
            const float lim = R2 - t2y;
            #pragma unroll
            for (int k = 0; k < NCOL; k++) {
                const float d2p = cP2[k] + p2y;
                const float w   = cEx[k] * ey;
                float d;
                asm("sqrt.approx.f32 %0, %1;" : "=f"(d) : "f"(d2p));
                const bool in = (cT2[k] <= lim);
                num0 += in ? w * d : 0.0f;
                den0 += in ? w     : 0.0f;
            }
        }
    }

    float num = num0 + num1;
    float den = den0 + den1;

    // Block reduction (8 warps) — uniform path for all blocks.
    #pragma unroll
    for (int o = 16; o; o >>= 1) {
        num += __shfl_xor_sync(0xffffffffu, num, o);
        den += __shfl_xor_sync(0xffffffffu, den, o);
    }
    if (cx == 0) { redN[cy] = num; redD[cy] = den; }
    __syncthreads();

    if (tid == 0) {
        float n = 0.0f, d = 0.0f;
        #pragma unroll
        for (int k = 0; k < 8; k++) { n += redN[k]; d += redD[k]; }
        g_partial[lm] = n / (d + 1e-8f);   // invisible: 0/1e-8 = 0
        __threadfence();
        const int c = atomicAdd(&g_count, 1);
        sIsLast = (c == BN - 1);
    }
    __syncthreads();

    // Last block folds all 512 partials into the scalar output.
    if (sIsLast) {
        float s = __ldcg(&g_partial[tid]) + __ldcg(&g_partial[tid + 256]);
        #pragma unroll
        for (int o = 16; o; o >>= 1) s += __shfl_xor_sync(0xffffffffu, s, o);
        if (cx == 0) redN[cy] = s;
        __syncthreads();
        if (tid == 0) {
            float t = 0.0f;
            #pragma unroll
            for (int k = 0; k < 8; k++) t += redN[k];
            *out = t / (512.0f + 1e-8f);
            g_count = 0;                   // reset for next graph replay
        }
    }
}

extern "C" void kernel_launch(void* const* d_in, const int* in_sizes, int n_in,
                              void* d_out, int out_size)
{
    const float* pred = (const float*)d_in[0];
    const float* tgt  = (const float*)d_in[1];
    const float* vis  = (const float*)d_in[2];
    const float* grid = (const float*)d_in[3];
    gkl_fused_kernel<<<BN, NTHR>>>(pred, tgt, vis, grid, (float*)d_out);
}

// round 7
// speedup vs baseline: 1.1032x; 1.0802x over previous
#include <cuda_runtime.h>
#include <cuda_bf16.h>

// GaussianKernelLoss: B=32, N=16, H=W=256, SIGMA=0.1, RADIUS=0.2
// d_in[0]=pred [32,16,2] f32, d_in[1]=target [32,16,2] f32,
// d_in[2]=visibility [32,16] f32, d_in[3]=coord_grid [2,256,256] f32 (linspace i/255)
// Output: scalar f32.

#define BN     512
#define NBLK   1024            // 2 row-split blocks per landmark
#define RADIUS 0.2f
#define R2     (0.2f * 0.2f)
#define COEF   (-50.0f)        // -1/(2*sigma^2)
#define INV255 (1.0f / 255.0f)
#define NCOL   4               // 4*32 = 128 >= max bbox width (~106)
#define NTHR   256             // 8 warps per block

__device__ float gN[NBLK];     // per-(landmark,split) numerator partials
__device__ float gD[NBLK];     // per-(landmark,split) denominator partials
__device__ int   g_count;      // zero-init; last block resets each launch

__global__ __launch_bounds__(NTHR)
void gkl_fused_kernel(const float* __restrict__ pred,
                      const float* __restrict__ tgt,
                      const float* __restrict__ vis,
                      const float* __restrict__ grid,
                      float* __restrict__ out)
{
    const int bid   = blockIdx.x;
    const int lm    = bid & (BN - 1);   // landmark 0..511
    const int split = bid >> 9;         // 0 or 1
    const int tid   = threadIdx.x;
    const int cx    = tid & 31;         // lane -> column subset
    const int cy    = tid >> 5;         // warp (0..7)
    const int wr    = cy + 8 * split;   // global warp-row residue 0..15

    __shared__ float redN[8], redD[8];
    __shared__ int   sIsLast;

    float num0 = 0.0f, den0 = 0.0f;     // independent accumulator chains
    float num1 = 0.0f, den1 = 0.0f;
    const float v = vis[lm];

    if (v >= 0.5f) {
        const float2 t2v = ((const float2*)tgt)[lm];
        const float2 p2v = ((const float2*)pred)[lm];
        const float tx = t2v.x, ty = t2v.y;
        const float px = p2v.x, py = p2v.y;

        // Bounding box of the radius disk (exact d<=R mask applied per-pixel).
        const int x0 = max(0,   (int)floorf((tx - RADIUS) * 255.0f) - 1);
        const int y0 = max(0,   (int)floorf((ty - RADIUS) * 255.0f) - 1);
        const int x1 = min(255, (int)ceilf ((tx + RADIUS) * 255.0f) + 1);
        const int y1 = min(255, (int)ceilf ((ty + RADIUS) * 255.0f) + 1);
        const int bw = x1 - x0 + 1;
        const int bh = y1 - y0 + 1;

        // Column tables in registers: lane cx owns columns cx + 32k.
        // Out-of-range columns poisoned (Ex=0, T2=huge) -> contribute 0.
        float cT2[NCOL], cP2[NCOL], cEx[NCOL];
        #pragma unroll
        for (int k = 0; k < NCOL; k++) {
            const int j   = cx + 32 * k;
            const bool ok = (j < bw);
            const float xv = (float)(x0 + j) * INV255;   // coord_grid == linspace
            const float dt = xv - tx;
            const float dp = xv - px;
            cT2[k] = ok ? dt * dt : 1e9f;
            cP2[k] = dp * dp;
            cEx[k] = ok ? __expf(COEF * dt * dt) : 0.0f;
        }

        // Row bases: dty = dty0 + i*INV255 (single FFMA per row).
        const float dty0 = (float)y0 * INV255 - ty;
        const float dpy0 = (float)y0 * INV255 - py;

        // Warp handles rows wr + 16n; unrolled x2 (rows i, i+16).
        int i = wr;
        for (; i + 16 < bh; i += 32) {
            {   // row i
                const float dty = fmaf((float)i, INV255, dty0);
                const float dpy = fmaf((float)i, INV255, dpy0);
                const float t2y = dty * dty;
                const float p2y = dpy * dpy;
                const float ey  = __expf(COEF * t2y);
                const float lim = R2 - t2y;
                #pragma unroll
                for (int k = 0; k < NCOL; k++) {
                    const float d2p = cP2[k] + p2y;
                    const float w   = cEx[k] * ey;
                    float d;
                    asm("sqrt.approx.f32 %0, %1;" : "=f"(d) : "f"(d2p));
                    const float wsel = (cT2[k] <= lim) ? w : 0.0f;
                    num0 = fmaf(wsel, d, num0);
                    den0 += wsel;
                }
            }
            {   // row i+16
                const int   i2  = i + 16;
                const float dty = fmaf((float)i2, INV255, dty0);
                const float dpy = fmaf((float)i2, INV255, dpy0);
                const float t2y = dty * dty;
                const float p2y = dpy * dpy;
                const float ey  = __expf(COEF * t2y);
                const float lim = R2 - t2y;
                #pragma unroll
                for (int k = 0; k < NCOL; k++) {
                    const float d2p = cP2[k] + p2y;
                    const float w   = cEx[k] * ey;
                    float d;
                    asm("sqrt.approx.f32 %0, %1;" : "=f"(d) : "f"(d2p));
                    const float wsel = (cT2[k] <= lim) ? w : 0.0f;
                    num1 = fmaf(wsel, d, num1);
                    den1 += wsel;
                }
            }
        }
        if (i < bh) {   // remainder row
            const float dty = fmaf((float)i, INV255, dty0);
            const float dpy = fmaf((float)i, INV255, dpy0);
            const float t2y = dty * dty;
            const float p2y = dpy * dpy;
            const float ey  = __expf(COEF * t2y);
            const float lim = R2 - t2y;
            #pragma unroll
            for (int k = 0; k < NCOL; k++) {
                const float d2p = cP2[k] + p2y;
                const float w   = cEx[k] * ey;
                float d;
                asm("sqrt.approx.f32 %0, %1;" : "=f"(d) : "f"(d2p));
                const float wsel = (cT2[k] <= lim) ? w : 0.0f;
                num0 = fmaf(wsel, d, num0);
                den0 += wsel;
            }
        }
    }

    float num = num0 + num1;
    float den = den0 + den1;

    // Block reduction (8 warps) — uniform path for all blocks.
    #pragma unroll
    for (int o = 16; o; o >>= 1) {
        num += __shfl_xor_sync(0xffffffffu, num, o);
        den += __shfl_xor_sync(0xffffffffu, den, o);
    }
    if (cx == 0) { redN[cy] = num; redD[cy] = den; }
    __syncthreads();

    if (tid == 0) {
        float n = 0.0f, d = 0.0f;
        #pragma unroll
        for (int k = 0; k < 8; k++) { n += redN[k]; d += redD[k]; }
        gN[bid] = n;
        gD[bid] = d;
        __threadfence();
        const int c = atomicAdd(&g_count, 1);
        sIsLast = (c == NBLK - 1);
    }
    __syncthreads();

    // Last block combines splits, divides per landmark, and sums.
    if (sIsLast) {
        float s = 0.0f;
        #pragma unroll
        for (int h = 0; h < 2; h++) {           // landmarks tid, tid+256
            const int l = tid + 256 * h;
            const float n = __ldcg(&gN[l]) + __ldcg(&gN[l + BN]);
            const float d = __ldcg(&gD[l]) + __ldcg(&gD[l + BN]);
            s += n / (d + 1e-8f);               // invisible: 0/1e-8 = 0
        }
        #pragma unroll
        for (int o = 16; o; o >>= 1) s += __shfl_xor_sync(0xffffffffu, s, o);
        if (cx == 0) redN[cy] = s;
        __syncthreads();
        if (tid == 0) {
            float t = 0.0f;
            #pragma unroll
            for (int k = 0; k < 8; k++) t += redN[k];
            *out = t / (512.0f + 1e-8f);
            g_count = 0;                        // reset for next graph replay
        }
    }
}

extern "C" void kernel_launch(void* const* d_in, const int* in_sizes, int n_in,
                              void* d_out, int out_size)
{
    const float* pred = (const float*)d_in[0];
    const float* tgt  = (const float*)d_in[1];
    const float* vis  = (const float*)d_in[2];
    const float* grid = (const float*)d_in[3];
    gkl_fused_kernel<<<NBLK, NTHR>>>(pred, tgt, vis, grid, (float*)d_out);
}

// round 9
// speedup vs baseline: 1.1702x; 1.0608x over previous
#include <cuda_runtime.h>
#include <cuda_bf16.h>

// GaussianKernelLoss: B=32, N=16, H=W=256, SIGMA=0.1, RADIUS=0.2
// d_in[0]=pred [32,16,2] f32, d_in[1]=target [32,16,2] f32,
// d_in[2]=visibility [32,16] f32, d_in[3]=coord_grid [2,256,256] f32 (linspace i/255)
// Output: scalar f32.

#define BN     512
#define RADIUS 0.2f
#define R2     (0.2f * 0.2f)
#define COEF   (-50.0f)        // -1/(2*sigma^2)
#define INV255 (1.0f / 255.0f)
#define NCOL   4               // 4*32 = 128 >= max bbox width (<=104 exact)
#define NTHR   256             // 8 warps per block, 1 landmark per block

__device__ float gN[BN];       // per-landmark numerator partials
__device__ float gD[BN];       // per-landmark denominator partials
__device__ int   g_count;      // zero-init; last block resets each launch

__global__ __launch_bounds__(NTHR)
void gkl_fused_kernel(const float* __restrict__ pred,
                      const float* __restrict__ tgt,
                      const float* __restrict__ vis,
                      const float* __restrict__ grid,
                      float* __restrict__ out)
{
    const int lm  = blockIdx.x;
    const int tid = threadIdx.x;
    const int cx  = tid & 31;   // lane -> column subset
    const int cy  = tid >> 5;   // warp (0..7) -> row residue (stride 8)

    __shared__ float redN[8], redD[8];
    __shared__ int   sIsLast;

    float num0 = 0.0f, den0 = 0.0f;     // two independent accumulator chains
    float num1 = 0.0f, den1 = 0.0f;
    const float v = vis[lm];

    if (v >= 0.5f) {
        const float2 t2v = ((const float2*)tgt)[lm];
        const float2 p2v = ((const float2*)pred)[lm];
        const float tx = t2v.x, ty = t2v.y;
        const float px = p2v.x, py = p2v.y;

        // Exact bounding box of the radius disk (per-pixel mask is exact).
        const int x0 = max(0,   (int)floorf((tx - RADIUS) * 255.0f));
        const int y0 = max(0,   (int)floorf((ty - RADIUS) * 255.0f));
        const int x1 = min(255, (int)ceilf ((tx + RADIUS) * 255.0f));
        const int y1 = min(255, (int)ceilf ((ty + RADIUS) * 255.0f));
        const int bw = x1 - x0 + 1;
        const int bh = y1 - y0 + 1;

        // Column tables in registers: lane cx owns columns cx + 32k.
        // Out-of-range columns poisoned (Ex=0, T2=huge) -> contribute 0.
        float cT2[NCOL], cP2[NCOL], cEx[NCOL];
        #pragma unroll
        for (int k = 0; k < NCOL; k++) {
            const int j   = cx + 32 * k;
            const bool ok = (j < bw);
            const float xv = (float)(x0 + j) * INV255;   // coord_grid == linspace
            const float dt = xv - tx;
            const float dp = xv - px;
            cT2[k] = ok ? dt * dt : 1e9f;
            cP2[k] = dp * dp;
            cEx[k] = ok ? __expf(COEF * dt * dt) : 0.0f;
        }

        // Incremental row coordinates: chain A = rows cy+16n, chain B = rows
        // cy+8+16n; both advanced by 16*INV255 per iteration (stride-8 overall).
        const float base = (float)y0 * INV255;
        float dtyA = fmaf((float)cy,       INV255, base - ty);
        float dpyA = fmaf((float)cy,       INV255, base - py);
        float dtyB = fmaf((float)(cy + 8), INV255, base - ty);
        float dpyB = fmaf((float)(cy + 8), INV255, base - py);
        const float STEP = 16.0f * INV255;

        int i = cy;
        for (; i + 8 < bh; i += 16) {
            {   // row i (chain A)
                const float t2y = dtyA * dtyA;
                const float p2y = dpyA * dpyA;
                const float ey  = __expf(COEF * t2y);
                const float lim = R2 - t2y;
                #pragma unroll
                for (int k = 0; k < NCOL; k++) {
                    const float d2p = cP2[k] + p2y;
                    const float w   = cEx[k] * ey;
                    float d;
                    asm("sqrt.approx.f32 %0, %1;" : "=f"(d) : "f"(d2p));
                    if (cT2[k] <= lim) {
                        num0 = fmaf(w, d, num0);
                        den0 += w;
                    }
                }
                dtyA += STEP; dpyA += STEP;
            }
            {   // row i+8 (chain B)
                const float t2y = dtyB * dtyB;
                const float p2y = dpyB * dpyB;
                const float ey  = __expf(COEF * t2y);
                const float lim = R2 - t2y;
                #pragma unroll
                for (int k = 0; k < NCOL; k++) {
                    const float d2p = cP2[k] + p2y;
                    const float w   = cEx[k] * ey;
                    float d;
                    asm("sqrt.approx.f32 %0, %1;" : "=f"(d) : "f"(d2p));
                    if (cT2[k] <= lim) {
                        num1 = fmaf(w, d, num1);
                        den1 += w;
                    }
                }
                dtyB += STEP; dpyB += STEP;
            }
        }
        if (i < bh) {   // remainder row (chain A)
            const float t2y = dtyA * dtyA;
            const float p2y = dpyA * dpyA;
            const float ey  = __expf(COEF * t2y);
            const float lim = R2 - t2y;
            #pragma unroll
            for (int k = 0; k < NCOL; k++) {
                const float d2p = cP2[k] + p2y;
                const float w   = cEx[k] * ey;
                float d;
                asm("sqrt.approx.f32 %0, %1;" : "=f"(d) : "f"(d2p));
                if (cT2[k] <= lim) {
                    num0 = fmaf(w, d, num0);
                    den0 += w;
                }
            }
        }
    }

    float num = num0 + num1;
    float den = den0 + den1;

    // Block reduction (8 warps) — uniform path for all blocks.
    #pragma unroll
    for (int o = 16; o; o >>= 1) {
        num += __shfl_xor_sync(0xffffffffu, num, o);
        den += __shfl_xor_sync(0xffffffffu, den, o);
    }
    if (cx == 0) { redN[cy] = num; redD[cy] = den; }
    __syncthreads();

    if (tid == 0) {
        float n = 0.0f, d = 0.0f;
        #pragma unroll
        for (int k = 0; k < 8; k++) { n += redN[k]; d += redD[k]; }
        gN[lm] = n;
        gD[lm] = d;
        __threadfence();
        const int c = atomicAdd(&g_count, 1);
        sIsLast = (c == BN - 1);
    }
    __syncthreads();

    // Last block divides per landmark and folds to the scalar output.
    if (sIsLast) {
        float s = 0.0f;
        #pragma unroll
        for (int h = 0; h < 2; h++) {           // landmarks tid, tid+256
            const int l = tid + 256 * h;
            const float n = __ldcg(&gN[l]);
            const float d = __ldcg(&gD[l]);
            s += n / (d + 1e-8f);               // invisible: 0/1e-8 = 0
        }
        #pragma unroll
        for (int o = 16; o; o >>= 1) s += __shfl_xor_sync(0xffffffffu, s, o);
        if (cx == 0) redN[cy] = s;
        __syncthreads();
        if (tid == 0) {
            float t = 0.0f;
            #pragma unroll
            for (int k = 0; k < 8; k++) t += redN[k];
            *out = t / (512.0f + 1e-8f);
            g_count = 0;                        // reset for next graph replay
        }
    }
}

extern "C" void kernel_launch(void* const* d_in, const int* in_sizes, int n_in,
                              void* d_out, int out_size)
{
    const float* pred = (const float*)d_in[0];
    const float* tgt  = (const float*)d_in[1];
    const float* vis  = (const float*)d_in[2];
    const float* grid = (const float*)d_in[3];
    gkl_fused_kernel<<<BN, NTHR>>>(pred, tgt, vis, grid, (float*)d_out);
}